// round 1
// baseline (speedup 1.0000x reference)
#include <cuda_runtime.h>
#include <cuda_bf16.h>
#include <math.h>

// Problem constants (match reference)
#define NN 50000
#define EE 1600000
#define FIN 256
#define HH 128
#define CC 40

// ---------------- device scratch (no allocs allowed) ----------------
__device__ __align__(16) float g_bufA[(size_t)NN * HH];
__device__ __align__(16) float g_bufB[(size_t)NN * HH];
__device__ float g_inv[NN];
__device__ int   g_deg[NN];
__device__ int   g_rowptr[NN + 1];
__device__ int   g_cursor[NN];
__device__ int   g_esrc[EE];
__device__ __align__(16) float g_ewt[EE];
__device__ float g_Wc[CC * CC];      // We @ Wf_top  (40x40)
__device__ float g_cbias[CC];        // bf + be @ Wf_top

// ---------------- row L2 norm (inverse, clamped) ----------------
__global__ void rownorm_kernel(const float* __restrict__ x, int n) {
    int w = (blockIdx.x * blockDim.x + threadIdx.x) >> 5;
    int lane = threadIdx.x & 31;
    if (w >= n) return;
    const float4* p = (const float4*)(x + (size_t)w * FIN);
    float4 a = p[lane];
    float4 b = p[lane + 32];
    float s = a.x*a.x + a.y*a.y + a.z*a.z + a.w*a.w
            + b.x*b.x + b.y*b.y + b.z*b.z + b.w*b.w;
    #pragma unroll
    for (int off = 16; off > 0; off >>= 1) s += __shfl_xor_sync(0xffffffffu, s, off);
    if (lane == 0) g_inv[w] = 1.0f / fmaxf(sqrtf(s), 1e-12f);
}

// ---------------- SGEMM: C[M x 128] = A[M x K] * B[K x 128], optional row scale ----------------
#define BM 128
#define BN 128
#define BK 16
#define TM 8
#define TN 8
template<bool SCALE>
__global__ __launch_bounds__(256) void gemm_kernel(
    const float* __restrict__ A, const float* __restrict__ B,
    float* __restrict__ C, int M, int K)
{
    __shared__ float As[BK][BM];
    __shared__ float Bs[BK][BN];
    int tid = threadIdx.x;
    int m0 = blockIdx.x * BM;
    int tx = tid & 15, ty = tid >> 4;
    float acc[TM][TN];
    #pragma unroll
    for (int i = 0; i < TM; i++)
        #pragma unroll
        for (int j = 0; j < TN; j++) acc[i][j] = 0.0f;

    for (int k0 = 0; k0 < K; k0 += BK) {
        #pragma unroll
        for (int i = 0; i < 2; i++) {
            int idx = tid + i * 256;        // 0..511
            int row = idx >> 2;             // 0..127
            int c4  = idx & 3;              // 0..3
            int gr = m0 + row;
            float4 v = make_float4(0.f, 0.f, 0.f, 0.f);
            if (gr < M) v = *(const float4*)(A + (size_t)gr * K + k0 + c4 * 4);
            As[c4 * 4 + 0][row] = v.x;
            As[c4 * 4 + 1][row] = v.y;
            As[c4 * 4 + 2][row] = v.z;
            As[c4 * 4 + 3][row] = v.w;
        }
        #pragma unroll
        for (int i = 0; i < 2; i++) {
            int idx = tid + i * 256;
            int row = idx >> 5;             // 0..15
            int c4  = idx & 31;
            float4 v = *(const float4*)(B + (size_t)(k0 + row) * BN + c4 * 4);
            *(float4*)&Bs[row][c4 * 4] = v;
        }
        __syncthreads();
        #pragma unroll
        for (int kk = 0; kk < BK; kk++) {
            float ra[TM], rb[TN];
            #pragma unroll
            for (int i = 0; i < TM; i++) ra[i] = As[kk][ty * TM + i];
            #pragma unroll
            for (int j = 0; j < TN; j++) rb[j] = Bs[kk][tx * TN + j];
            #pragma unroll
            for (int i = 0; i < TM; i++)
                #pragma unroll
                for (int j = 0; j < TN; j++) acc[i][j] += ra[i] * rb[j];
        }
        __syncthreads();
    }
    #pragma unroll
    for (int i = 0; i < TM; i++) {
        int gr = m0 + ty * TM + i;
        if (gr >= M) continue;
        float s = SCALE ? g_inv[gr] : 1.0f;
        #pragma unroll
        for (int j = 0; j < TN; j += 4) {
            float4 v;
            v.x = acc[i][j + 0] * s;
            v.y = acc[i][j + 1] * s;
            v.z = acc[i][j + 2] * s;
            v.w = acc[i][j + 3] * s;
            *(float4*)(C + (size_t)gr * BN + tx * TN + j) = v;
        }
    }
}

// ---------------- CSR build ----------------
__global__ void zero_deg_kernel(int n) {
    int i = blockIdx.x * blockDim.x + threadIdx.x;
    if (i < n) g_deg[i] = 0;
}
__global__ void hist_kernel(const int* __restrict__ dst, int e) {
    int i = blockIdx.x * blockDim.x + threadIdx.x;
    if (i < e) atomicAdd(&g_deg[dst[i]], 1);
}
__global__ void scan_kernel(int n) {
    __shared__ int wsum[32];
    __shared__ int s_run;
    int tid = threadIdx.x, lane = tid & 31, wid = tid >> 5;
    if (tid == 0) s_run = 0;
    __syncthreads();
    for (int base = 0; base < n; base += 1024) {
        int idx = base + tid;
        int v = (idx < n) ? g_deg[idx] : 0;
        int inc = v;
        #pragma unroll
        for (int off = 1; off < 32; off <<= 1) {
            int t = __shfl_up_sync(0xffffffffu, inc, off);
            if (lane >= off) inc += t;
        }
        if (lane == 31) wsum[wid] = inc;
        __syncthreads();
        if (wid == 0) {
            int x = wsum[lane];
            #pragma unroll
            for (int off = 1; off < 32; off <<= 1) {
                int t = __shfl_up_sync(0xffffffffu, x, off);
                if (lane >= off) x += t;
            }
            wsum[lane] = x;
        }
        __syncthreads();
        int woff = (wid > 0) ? wsum[wid - 1] : 0;
        int run = s_run;
        int excl = run + woff + inc - v;
        if (idx < n) { g_rowptr[idx] = excl; g_cursor[idx] = excl; }
        __syncthreads();
        if (tid == 0) s_run = run + wsum[31];
        __syncthreads();
    }
    if (threadIdx.x == 0) g_rowptr[n] = s_run;
}
__global__ void scatter_kernel(const int* __restrict__ src, const int* __restrict__ dst,
                               const float* __restrict__ w, int e) {
    int i = blockIdx.x * blockDim.x + threadIdx.x;
    if (i < e) {
        int d = dst[i];
        int pos = atomicAdd(&g_cursor[d], 1);
        g_esrc[pos] = src[i];
        g_ewt[pos]  = w[i];
    }
}

// ---------------- SPMM gather: out[r] = sum_e w*x[src] (+bias, optional relu) ----------------
template<bool RELU>
__global__ void spmm_kernel(const float* __restrict__ x, float* __restrict__ out,
                            const float* __restrict__ bias, int n)
{
    int w = (blockIdx.x * blockDim.x + threadIdx.x) >> 5;
    int lane = threadIdx.x & 31;
    if (w >= n) return;
    int e0 = g_rowptr[w], e1 = g_rowptr[w + 1];
    float4 acc = make_float4(0.f, 0.f, 0.f, 0.f);
    const float4* xv = (const float4*)x;
    int e = e0;
    for (; e + 4 <= e1; e += 4) {
        int i0 = g_esrc[e], i1 = g_esrc[e + 1], i2 = g_esrc[e + 2], i3 = g_esrc[e + 3];
        float w0 = g_ewt[e], w1 = g_ewt[e + 1], w2 = g_ewt[e + 2], w3 = g_ewt[e + 3];
        float4 v0 = xv[(size_t)i0 * 32 + lane];
        float4 v1 = xv[(size_t)i1 * 32 + lane];
        float4 v2 = xv[(size_t)i2 * 32 + lane];
        float4 v3 = xv[(size_t)i3 * 32 + lane];
        acc.x += w0 * v0.x; acc.y += w0 * v0.y; acc.z += w0 * v0.z; acc.w += w0 * v0.w;
        acc.x += w1 * v1.x; acc.y += w1 * v1.y; acc.z += w1 * v1.z; acc.w += w1 * v1.w;
        acc.x += w2 * v2.x; acc.y += w2 * v2.y; acc.z += w2 * v2.z; acc.w += w2 * v2.w;
        acc.x += w3 * v3.x; acc.y += w3 * v3.y; acc.z += w3 * v3.z; acc.w += w3 * v3.w;
    }
    for (; e < e1; e++) {
        int i0 = g_esrc[e];
        float w0 = g_ewt[e];
        float4 v0 = xv[(size_t)i0 * 32 + lane];
        acc.x += w0 * v0.x; acc.y += w0 * v0.y; acc.z += w0 * v0.z; acc.w += w0 * v0.w;
    }
    float4 bv = ((const float4*)bias)[lane];
    acc.x += bv.x; acc.y += bv.y; acc.z += bv.z; acc.w += bv.w;
    if (RELU) {
        acc.x = fmaxf(acc.x, 0.f); acc.y = fmaxf(acc.y, 0.f);
        acc.z = fmaxf(acc.z, 0.f); acc.w = fmaxf(acc.w, 0.f);
    }
    ((float4*)out)[(size_t)w * 32 + lane] = acc;
}

// ---------------- head weight pre-combine: Wc = We @ Wf[0:128], cbias = bf + be @ Wf[0:128] ----------------
__global__ void wcomb_kernel(const float* __restrict__ We, const float* __restrict__ be,
                             const float* __restrict__ Wf, const float* __restrict__ bf)
{
    int t = blockIdx.x * blockDim.x + threadIdx.x;
    if (t < CC * CC) {
        int i = t / CC, c = t % CC;
        float s = 0.f;
        for (int k = 0; k < HH; k++) s += We[i * HH + k] * Wf[k * CC + c];
        g_Wc[t] = s;
    }
    if (t < CC) {
        float s = bf[t];
        for (int k = 0; k < HH; k++) s += be[k] * Wf[k * CC + t];
        g_cbias[t] = s;
    }
}

// ---------------- fused head: logits = y@Wc + h@Wf_bot + cbias ; softmax ----------------
__global__ __launch_bounds__(128) void head_kernel(
    const float* __restrict__ h, const float* __restrict__ yin,
    const float* __restrict__ Wf, float* __restrict__ out, int n)
{
    __shared__ float sWfb[HH * CC];   // 20480 B
    __shared__ float sWc[CC * CC];    // 6400 B
    __shared__ float sh[32 * HH];     // 16384 B
    __shared__ float sl[32 * CC];     // 5120 B
    __shared__ float smax[32], sinv[32];
    int tid = threadIdx.x;
    int r0 = blockIdx.x * 32;
    int rows = min(32, n - r0);

    for (int i = tid; i < HH * CC; i += 128) sWfb[i] = Wf[HH * CC + i];
    for (int i = tid; i < CC * CC; i += 128) sWc[i] = g_Wc[i];
    for (int i = tid; i < rows * HH; i += 128) sh[i] = h[(size_t)r0 * HH + i];
    __syncthreads();

    int r = tid >> 2, q = tid & 3, c0 = q * 10;
    if (r < rows) {
        float acc[10];
        #pragma unroll
        for (int j = 0; j < 10; j++) acc[j] = g_cbias[c0 + j];
        for (int k = 0; k < HH; k++) {
            float hv = sh[r * HH + k];
            #pragma unroll
            for (int j = 0; j < 10; j++) acc[j] += hv * sWfb[k * CC + c0 + j];
        }
        const float* yr = yin + (size_t)(r0 + r) * CC;
        for (int k = 0; k < CC; k++) {
            float yv = yr[k];
            #pragma unroll
            for (int j = 0; j < 10; j++) acc[j] += yv * sWc[k * CC + c0 + j];
        }
        #pragma unroll
        for (int j = 0; j < 10; j++) sl[r * CC + c0 + j] = acc[j];
    }
    __syncthreads();
    if (tid < 32 && tid < rows) {
        float m = -1e30f;
        for (int c = 0; c < CC; c++) m = fmaxf(m, sl[tid * CC + c]);
        float s = 0.f;
        for (int c = 0; c < CC; c++) s += __expf(sl[tid * CC + c] - m);
        smax[tid] = m;
        sinv[tid] = 1.0f / s;
    }
    __syncthreads();
    int tot = rows * CC;
    for (int i = tid; i < tot; i += 128) {
        int rr = i / CC;
        out[(size_t)r0 * CC + i] = __expf(sl[i] - smax[rr]) * sinv[rr];
    }
}

// ---------------- launch ----------------
extern "C" void kernel_launch(void* const* d_in, const int* in_sizes, int n_in,
                              void* d_out, int out_size)
{
    const float* features = (const float*)d_in[0];
    const int*   src      = (const int*)  d_in[1];
    const int*   dst      = (const int*)  d_in[2];
    const float* ew       = (const float*)d_in[3];
    const float* y        = (const float*)d_in[4];
    const float* W1       = (const float*)d_in[5];
    const float* b1       = (const float*)d_in[6];
    const float* W2       = (const float*)d_in[7];
    const float* b2       = (const float*)d_in[8];
    const float* We       = (const float*)d_in[9];
    const float* be       = (const float*)d_in[10];
    const float* Wf       = (const float*)d_in[11];
    const float* bf       = (const float*)d_in[12];
    float* out = (float*)d_out;

    int n = in_sizes[0] / FIN;     // 50000
    int e = in_sizes[1];           // 1600000

    int warpBlocks = (n + 7) / 8;          // 8 warps per 256-thread block
    int edgeBlocks = (e + 255) / 256;
    int mTiles     = (n + BM - 1) / BM;

    // normalization scale + GEMM1 (scaled by 1/||x||)
    rownorm_kernel<<<warpBlocks, 256>>>(features, n);
    gemm_kernel<true><<<mTiles, 256>>>(features, W1, g_bufA, n, FIN);

    // CSR by dst
    zero_deg_kernel<<<(n + 255) / 256, 256>>>(n);
    hist_kernel<<<edgeBlocks, 256>>>(dst, e);
    scan_kernel<<<1, 1024>>>(n);
    scatter_kernel<<<edgeBlocks, 256>>>(src, dst, ew, e);

    // layer 1 aggregate + relu
    spmm_kernel<true><<<warpBlocks, 256>>>(g_bufA, g_bufB, b1, n);
    // layer 2
    gemm_kernel<false><<<mTiles, 256>>>(g_bufB, W2, g_bufA, n, HH);
    spmm_kernel<false><<<warpBlocks, 256>>>(g_bufA, g_bufB, b2, n);

    // head
    wcomb_kernel<<<7, 256>>>(We, be, Wf, bf);
    head_kernel<<<(n + 31) / 32, 128>>>(g_bufB, y, Wf, out, n);
}